// round 15
// baseline (speedup 1.0000x reference)
#include <cuda_runtime.h>
#include <cuda_fp16.h>
#include <stdint.h>

#define BATCH 16
#define SEQ   2048
#define DIM   128
#define NT    256
#define KTILES 32
#define NKT_JOB 8
#define NQT   256
#define NJOBS (NQT * 4)
#define GRID  148

#define STAGE_B    32768u
#define QW_OFF     131072
#define QW2_OFF    131076
#define SMEM_BYTES 131104

__device__ uint2 g_K16[BATCH * SEQ * DIM / 4];
__device__ uint2 g_V16[BATCH * SEQ * DIM / 4];
__device__ float g_meanV[BATCH][DIM];
__device__ float g_part[64][BATCH][DIM];
__device__ float g_Opart[NQT][4][128 * 128];   // 64 MB split-K partials
__device__ float g_lpart[NQT][4][128];
__device__ int   g_done[NQT];
__device__ int   g_q1;

// ---------------------------------------------------------------------------
__device__ __forceinline__ float ex2(float x) {
    float y;
    asm("ex2.approx.f32 %0, %1;" : "=f"(y) : "f"(x));
    return y;
}
__device__ __forceinline__ uint32_t smem_u32(const void* p) {
    uint32_t a;
    asm("{ .reg .u64 t; cvta.to.shared.u64 t, %1; cvt.u32.u64 %0, t; }" : "=r"(a) : "l"(p));
    return a;
}
__device__ __forceinline__ void cp16(uint32_t dst, const void* src) {
    asm volatile("cp.async.cg.shared.global [%0], [%1], 16;" :: "r"(dst), "l"(src));
}
__device__ __forceinline__ uint32_t pkh(float lo, float hi) {
    uint32_t r;
    asm("cvt.rn.f16x2.f32 %0, %1, %2;" : "=r"(r) : "f"(hi), "f"(lo));
    return r;
}
__device__ __forceinline__ void mma16(float* c, const uint32_t* a, uint32_t b0, uint32_t b1) {
    asm volatile(
        "mma.sync.aligned.m16n8k16.row.col.f32.f16.f16.f32 "
        "{%0,%1,%2,%3}, {%4,%5,%6,%7}, {%8,%9}, {%0,%1,%2,%3};"
        : "+f"(c[0]), "+f"(c[1]), "+f"(c[2]), "+f"(c[3])
        : "r"(a[0]), "r"(a[1]), "r"(a[2]), "r"(a[3]), "r"(b0), "r"(b1));
}
__device__ __forceinline__ void ldsm4(uint32_t* r, uint32_t a) {
    asm volatile("ldmatrix.sync.aligned.m8n8.x4.shared.b16 {%0,%1,%2,%3}, [%4];"
        : "=r"(r[0]), "=r"(r[1]), "=r"(r[2]), "=r"(r[3]) : "r"(a));
}
__device__ __forceinline__ void ldsm4t(uint32_t* r, uint32_t a) {
    asm volatile("ldmatrix.sync.aligned.m8n8.x4.trans.shared.b16 {%0,%1,%2,%3}, [%4];"
        : "=r"(r[0]), "=r"(r[1]), "=r"(r[2]), "=r"(r[3]) : "r"(a));
}

// ---------------------------------------------------------------------------
// cvt_kernel: K,V fp32 -> fp16 (16B stores) + V column-sum partials. 1024 CTAs.
// ---------------------------------------------------------------------------
__global__ void cvt_kernel(const float* __restrict__ K, const float* __restrict__ V) {
    __shared__ float red[NT * 8];
    const int tid = threadIdx.x;
    const int b   = blockIdx.x >> 6;
    const int sl  = blockIdx.x & 63;
    const size_t fbase = ((size_t)b * SEQ + (size_t)sl * 32) * DIM;
    const float4* k4 = (const float4*)(K + fbase);
    const float4* v4 = (const float4*)(V + fbase);
    uint4* ko = (uint4*)(g_K16 + fbase / 4);
    uint4* vo = (uint4*)(g_V16 + fbase / 4);

    float4 ka[4], va[4];
    #pragma unroll
    for (int i = 0; i < 2; ++i) {
        int t8 = i * NT + tid;
        ka[2*i]   = k4[t8 * 2];
        ka[2*i+1] = k4[t8 * 2 + 1];
        va[2*i]   = v4[t8 * 2];
        va[2*i+1] = v4[t8 * 2 + 1];
    }
    float vs[8];
    #pragma unroll
    for (int j = 0; j < 8; ++j) vs[j] = 0.f;
    #pragma unroll
    for (int i = 0; i < 2; ++i) {
        int t8 = i * NT + tid;
        ko[t8] = make_uint4(pkh(ka[2*i].x, ka[2*i].y),   pkh(ka[2*i].z, ka[2*i].w),
                            pkh(ka[2*i+1].x, ka[2*i+1].y), pkh(ka[2*i+1].z, ka[2*i+1].w));
        vo[t8] = make_uint4(pkh(va[2*i].x, va[2*i].y),   pkh(va[2*i].z, va[2*i].w),
                            pkh(va[2*i+1].x, va[2*i+1].y), pkh(va[2*i+1].z, va[2*i+1].w));
        vs[0] += va[2*i].x; vs[1] += va[2*i].y; vs[2] += va[2*i].z; vs[3] += va[2*i].w;
        vs[4] += va[2*i+1].x; vs[5] += va[2*i+1].y; vs[6] += va[2*i+1].z; vs[7] += va[2*i+1].w;
    }
    #pragma unroll
    for (int j = 0; j < 8; ++j) red[tid * 8 + j] = vs[j];
    __syncthreads();
    if (tid < 16) {
        float s[8];
        #pragma unroll
        for (int j = 0; j < 8; ++j) s[j] = 0.f;
        #pragma unroll
        for (int g = 0; g < 16; ++g)
            #pragma unroll
            for (int j = 0; j < 8; ++j) s[j] += red[(g * 16 + tid) * 8 + j];
        #pragma unroll
        for (int j = 0; j < 8; ++j) g_part[sl][b][tid * 8 + j] = s[j];
    }
}

__global__ void meanv_final() {
    int b = blockIdx.x;
    int d = threadIdx.x;
    float s = 0.f;
    #pragma unroll
    for (int i = 0; i < 64; ++i) s += g_part[i][b][d];
    g_meanV[b][d] = s * (1.0f / SEQ);
    int idx = b * DIM + d;
    if (idx < NQT) g_done[idx] = 0;
    if (idx == 0)  g_q1 = 0;
}

// ---------------------------------------------------------------------------
// Persistent split-K flash attention: 148 CTAs work-steal (q-tile, k-quarter)
// jobs (8 ktiles each, ~8us). Unnormalized O / l partials compose linearly
// (no online max); last finisher per tile reduces in fixed quarter order.
// ---------------------------------------------------------------------------
__global__ __launch_bounds__(NT, 1)
void attn_kernel(const float* __restrict__ Qg, const int* __restrict__ vlg,
                 float* __restrict__ Og)
{
    extern __shared__ char smem[];
    const int tid  = threadIdx.x;
    const int lane = tid & 31;
    const int w    = tid >> 5;
    const int qr   = lane >> 2;
    const int qc   = lane & 3;
    const uint32_t sbase = smem_u32(smem);
    volatile int* qw  = (volatile int*)(smem + QW_OFF);
    volatile int* qw2 = (volatile int*)(smem + QW2_OFF);

    const uint32_t csrc = (uint32_t)(tid & 15) * 16u;
    const uint32_t r0t  = (uint32_t)(tid >> 4);
    const uint32_t swz  = (uint32_t)((tid & 15) ^ (int)(r0t & 7)) << 4;
    const uint32_t r7 = (uint32_t)(lane & 7);
    const int      lt = lane >> 3;
    const uint32_t kL = sbase + r7 * 256u;
    const uint32_t vL = sbase + 16384u + (uint32_t)(8 * (lt & 1)) * 256u + r7 * 256u;
    const float qscale = 0.088388347648318447f * 1.4426950408889634f;

    for (;;) {
        if (tid == 0) *qw = atomicAdd(&g_q1, 1);
        __syncthreads();
        const int j = *qw;
        __syncthreads();
        if (j >= NJOBS) break;

        const int tile = j >> 2;
        const int qt   = j & 3;
        const int b    = tile & 15;
        const int q0   = (tile >> 4) * 128;
        const int vl   = vlg[b];

        // ---- masked q-tile: quarter 0 writes meanV rows, others nop ----
        if (q0 >= vl) {
            if (qt == 0) {
                int row = tid >> 1, hh = tid & 1;
                const float4* mv = (const float4*)&g_meanV[b][hh * 64];
                float4* o4 = (float4*)(Og + ((size_t)b * SEQ + q0 + row) * DIM + hh * 64);
                #pragma unroll
                for (int jj = 0; jj < 16; ++jj) o4[jj] = mv[jj];
            }
            continue;
        }

        // ---- heavy quarter job: ktiles [8qt, 8qt+8) ----
        asm volatile("cp.async.wait_group 0;" ::: "memory");

        const uint8_t* kb16 = (const uint8_t*)g_K16 + (size_t)b * SEQ * DIM * 2 + (size_t)qt * 8 * 16384;
        const uint8_t* vb16 = (const uint8_t*)g_V16 + (size_t)b * SEQ * DIM * 2 + (size_t)qt * 8 * 16384;

        #pragma unroll
        for (int t = 0; t < 3; ++t) {
            const uint8_t* ks = kb16 + (size_t)t * 16384;
            const uint8_t* vs = vb16 + (size_t)t * 16384;
            uint32_t stg = (uint32_t)t * STAGE_B;
            #pragma unroll
            for (int i = 0; i < 4; ++i) {
                uint32_t r = (uint32_t)i * 16u + r0t;
                cp16(sbase + stg + r * 256u + swz, ks + r * 256u + csrc);
                cp16(sbase + stg + 16384u + r * 256u + swz, vs + r * 256u + csrc);
            }
            asm volatile("cp.async.commit_group;");
        }

        uint32_t qa[8][4];
        {
            const float* r0 = Qg + ((size_t)b * SEQ + q0 + w * 16 + qr) * DIM;
            const float* r1 = r0 + 8 * DIM;
            #pragma unroll
            for (int kb = 0; kb < 8; ++kb) {
                int d0 = kb * 16 + 2 * qc;
                float2 a = *(const float2*)(r0 + d0);
                float2 c = *(const float2*)(r1 + d0);
                float2 e = *(const float2*)(r0 + d0 + 8);
                float2 f = *(const float2*)(r1 + d0 + 8);
                qa[kb][0] = pkh(a.x * qscale, a.y * qscale);
                qa[kb][1] = pkh(c.x * qscale, c.y * qscale);
                qa[kb][2] = pkh(e.x * qscale, e.y * qscale);
                qa[kb][3] = pkh(f.x * qscale, f.y * qscale);
            }
        }

        float o[16][4];
        #pragma unroll
        for (int n = 0; n < 16; ++n) { o[n][0] = o[n][1] = o[n][2] = o[n][3] = 0.f; }
        float l0 = 0.f, l1 = 0.f;

        for (int kt = 0; kt < NKT_JOB; ++kt) {
            asm volatile("cp.async.wait_group 2;" ::: "memory");
            __syncthreads();

            if (kt + 3 < NKT_JOB) {
                const uint32_t nb = (uint32_t)((kt + 3) & 3) * STAGE_B;
                const uint8_t* ks = kb16 + (size_t)(kt + 3) * 16384;
                const uint8_t* vs = vb16 + (size_t)(kt + 3) * 16384;
                #pragma unroll
                for (int i = 0; i < 4; ++i) {
                    uint32_t r = (uint32_t)i * 16u + r0t;
                    cp16(sbase + nb + r * 256u + swz, ks + r * 256u + csrc);
                    cp16(sbase + nb + 16384u + r * 256u + swz, vs + r * 256u + csrc);
                }
            }
            asm volatile("cp.async.commit_group;");

            const uint32_t stg = (uint32_t)(kt & 3) * STAGE_B;

            float sacc[8][4];
            #pragma unroll
            for (int n = 0; n < 8; ++n) { sacc[n][0] = sacc[n][1] = sacc[n][2] = sacc[n][3] = 0.f; }
            #pragma unroll
            for (int nb = 0; nb < 8; ++nb) {
                uint32_t abase = kL + stg + (uint32_t)(nb * 8) * 256u;
                #pragma unroll
                for (int g = 0; g < 4; ++g) {
                    uint32_t r[4];
                    ldsm4(r, abase + ((((uint32_t)(4 * g + lt)) ^ r7) << 4));
                    mma16(sacc[nb], qa[2 * g],     r[0], r[1]);
                    mma16(sacc[nb], qa[2 * g + 1], r[2], r[3]);
                }
            }

            uint32_t pa[4][4];
            #pragma unroll
            for (int kb = 0; kb < 4; ++kb) {
                float e00 = ex2(sacc[2 * kb][0]),     e01 = ex2(sacc[2 * kb][1]);
                float e02 = ex2(sacc[2 * kb][2]),     e03 = ex2(sacc[2 * kb][3]);
                float e10 = ex2(sacc[2 * kb + 1][0]), e11 = ex2(sacc[2 * kb + 1][1]);
                float e12 = ex2(sacc[2 * kb + 1][2]), e13 = ex2(sacc[2 * kb + 1][3]);
                l0 += (e00 + e01) + (e10 + e11);
                l1 += (e02 + e03) + (e12 + e13);
                pa[kb][0] = pkh(e00, e01);
                pa[kb][1] = pkh(e02, e03);
                pa[kb][2] = pkh(e10, e11);
                pa[kb][3] = pkh(e12, e13);
            }

            #pragma unroll
            for (int np = 0; np < 8; ++np) {
                uint32_t coff = (((uint32_t)(2 * np + (lt >> 1))) ^ r7) << 4;
                #pragma unroll
                for (int kb = 0; kb < 4; ++kb) {
                    uint32_t r[4];
                    ldsm4t(r, vL + stg + (uint32_t)kb * 4096u + coff);
                    mma16(o[2 * np],     pa[kb], r[0], r[1]);
                    mma16(o[2 * np + 1], pa[kb], r[2], r[3]);
                }
            }
        }

        // ---- write partials (unnormalized O + l) ----
        l0 += __shfl_xor_sync(0xffffffffu, l0, 1);
        l0 += __shfl_xor_sync(0xffffffffu, l0, 2);
        l1 += __shfl_xor_sync(0xffffffffu, l1, 1);
        l1 += __shfl_xor_sync(0xffffffffu, l1, 2);

        float* Op = g_Opart[tile][qt];
        const int row0 = w * 16 + qr;
        const int row1 = row0 + 8;
        #pragma unroll
        for (int n = 0; n < 16; ++n) {
            int col = n * 8 + 2 * qc;
            *(float2*)(Op + row0 * 128 + col) = make_float2(o[n][0], o[n][1]);
            *(float2*)(Op + row1 * 128 + col) = make_float2(o[n][2], o[n][3]);
        }
        if (qc == 0) {
            g_lpart[tile][qt][row0] = l0;
            g_lpart[tile][qt][row1] = l1;
        }
        __threadfence();
        __syncthreads();
        if (tid == 0) *qw2 = atomicAdd(&g_done[tile], 1);
        __syncthreads();

        // ---- last finisher: reduce 4 quarters, normalize, mask, store ----
        if (*qw2 == 3) {
            __threadfence();
            const int row  = tid >> 1;
            const int half = tid & 1;
            const int grow = q0 + row;
            float4* outp = (float4*)(Og + ((size_t)b * SEQ + grow) * DIM + half * 64);
            if (grow >= vl) {
                const float4* mv = (const float4*)&g_meanV[b][half * 64];
                #pragma unroll
                for (int c = 0; c < 16; ++c) outp[c] = mv[c];
            } else {
                float lsum = (g_lpart[tile][0][row] + g_lpart[tile][1][row]) +
                             (g_lpart[tile][2][row] + g_lpart[tile][3][row]);
                float inv = 1.0f / lsum;
                const float4* p0 = (const float4*)(g_Opart[tile][0] + row * 128 + half * 64);
                const float4* p1 = (const float4*)(g_Opart[tile][1] + row * 128 + half * 64);
                const float4* p2 = (const float4*)(g_Opart[tile][2] + row * 128 + half * 64);
                const float4* p3 = (const float4*)(g_Opart[tile][3] + row * 128 + half * 64);
                #pragma unroll
                for (int c = 0; c < 16; ++c) {
                    float4 a = p0[c], bb = p1[c], cc = p2[c], dd = p3[c];
                    outp[c] = make_float4(((a.x + bb.x) + (cc.x + dd.x)) * inv,
                                          ((a.y + bb.y) + (cc.y + dd.y)) * inv,
                                          ((a.z + bb.z) + (cc.z + dd.z)) * inv,
                                          ((a.w + bb.w) + (cc.w + dd.w)) * inv);
                }
            }
        }
    }
}

extern "C" void kernel_launch(void* const* d_in, const int* in_sizes, int n_in,
                              void* d_out, int out_size) {
    const float* Q  = (const float*)d_in[0];
    const float* K  = (const float*)d_in[1];
    const float* V  = (const float*)d_in[2];
    const int*   vl = (const int*)d_in[3];
    float* out = (float*)d_out;

    cvt_kernel<<<BATCH * 64, NT>>>(K, V);
    meanv_final<<<BATCH, DIM>>>();

    cudaFuncSetAttribute(attn_kernel, cudaFuncAttributeMaxDynamicSharedMemorySize, SMEM_BYTES);
    attn_kernel<<<GRID, NT, SMEM_BYTES>>>(Q, vl, out);
}